// round 1
// baseline (speedup 1.0000x reference)
#include <cuda_runtime.h>
#include <math.h>

// ---------------- problem constants ----------------
#define BGPT 4
#define TGPT 1024
#define DGPT 1024
#define HGPT 16
#define HDH  64
#define LGPT 8
#define VGPT 4096
#define MGPT (BGPT*TGPT)   // 4096 tokens
#define FGPT (4*DGPT)      // 4096 ff dim

// ---------------- scratch (device globals; no allocs allowed) ----------------
__device__ float g_x [MGPT*DGPT];   // residual stream
__device__ float g_h [MGPT*DGPT];   // LN out / attn out
__device__ float g_q [MGPT*DGPT];
__device__ float g_k [MGPT*DGPT];
__device__ float g_v [MGPT*DGPT];
__device__ float g_ff[MGPT*FGPT];

// ---------------- embedding: x = tok_emb[idx] + pos_emb ----------------
__global__ void embed_kernel(const int* __restrict__ idx,
                             const float* __restrict__ tok,
                             const float* __restrict__ pos,
                             float* __restrict__ x)
{
    int i = blockIdx.x * blockDim.x + threadIdx.x;
    if (i >= MGPT * DGPT) return;
    int row = i / DGPT;
    int d   = i - row * DGPT;
    int t   = row & (TGPT - 1);
    x[i] = tok[(size_t)idx[row] * DGPT + d] + pos[(size_t)t * DGPT + d];
}

// ---------------- layernorm (one block per row, 256 threads) ----------------
__global__ void __launch_bounds__(256) ln_kernel(const float* __restrict__ in,
                                                 float* __restrict__ out,
                                                 const float* __restrict__ w,
                                                 const float* __restrict__ b)
{
    int row = blockIdx.x;
    const float* x = in + (size_t)row * DGPT;
    int tid = threadIdx.x;
    __shared__ float red[8];

    float s = 0.f;
    for (int d = tid; d < DGPT; d += 256) s += x[d];
    #pragma unroll
    for (int o = 16; o; o >>= 1) s += __shfl_xor_sync(0xffffffffu, s, o);
    if ((tid & 31) == 0) red[tid >> 5] = s;
    __syncthreads();
    if (tid < 32) {
        float v = (tid < 8) ? red[tid] : 0.f;
        #pragma unroll
        for (int o = 4; o; o >>= 1) v += __shfl_xor_sync(0xffffffffu, v, o);
        if (tid == 0) red[0] = v;
    }
    __syncthreads();
    float mean = red[0] * (1.f / DGPT);

    float q = 0.f;
    for (int d = tid; d < DGPT; d += 256) { float t = x[d] - mean; q += t * t; }
    __syncthreads();  // everyone has read red[0]
    #pragma unroll
    for (int o = 16; o; o >>= 1) q += __shfl_xor_sync(0xffffffffu, q, o);
    if ((tid & 31) == 0) red[tid >> 5] = q;
    __syncthreads();
    if (tid < 32) {
        float v = (tid < 8) ? red[tid] : 0.f;
        #pragma unroll
        for (int o = 4; o; o >>= 1) v += __shfl_xor_sync(0xffffffffu, v, o);
        if (tid == 0) red[0] = v;
    }
    __syncthreads();
    float rstd = rsqrtf(red[0] * (1.f / DGPT) + 1e-5f);

    for (int d = tid; d < DGPT; d += 256)
        out[(size_t)row * DGPT + d] = (x[d] - mean) * rstd * w[d] + b[d];
}

// ---------------- GEMM: C[M,N] = A[M,K] @ W[N,K]^T (+bias)(+gelu)(+res) ----
// MODE: 0 = +bias  |  1 = +bias then exact GELU  |  2 = +bias +res  |  3 = plain
template<int MODE>
__global__ void __launch_bounds__(256) gemm_kernel(const float* __restrict__ A,
                                                   const float* __restrict__ W,
                                                   const float* __restrict__ bias,
                                                   const float* __restrict__ res,
                                                   float* __restrict__ C,
                                                   int M, int N, int K)
{
    const int BM = 128, BN = 128, BK = 8;
    __shared__ __align__(16) float As[BK][BM];
    __shared__ __align__(16) float Bs[BK][BN];

    int bm = blockIdx.y * BM;
    int bn = blockIdx.x * BN;
    int tid = threadIdx.x;

    int row0 = (tid / 16) * 8;      // within-tile output row base
    int col0 = (tid % 16) * 8;      // within-tile output col base

    float acc[8][8];
    #pragma unroll
    for (int i = 0; i < 8; i++)
        #pragma unroll
        for (int j = 0; j < 8; j++) acc[i][j] = 0.f;

    int lr = tid >> 1;              // 0..127 load row
    int lc = (tid & 1) * 4;         // 0 or 4 k-offset
    const float* Aptr = A + (size_t)(bm + lr) * K + lc;
    const float* Wptr = W + (size_t)(bn + lr) * K + lc;

    for (int k0 = 0; k0 < K; k0 += BK) {
        float4 a = *(const float4*)(Aptr + k0);
        float4 w = *(const float4*)(Wptr + k0);
        As[lc + 0][lr] = a.x; As[lc + 1][lr] = a.y;
        As[lc + 2][lr] = a.z; As[lc + 3][lr] = a.w;
        Bs[lc + 0][lr] = w.x; Bs[lc + 1][lr] = w.y;
        Bs[lc + 2][lr] = w.z; Bs[lc + 3][lr] = w.w;
        __syncthreads();

        #pragma unroll
        for (int kk = 0; kk < BK; kk++) {
            float ra[8], rb[8];
            *(float4*)(ra)     = *(const float4*)&As[kk][row0];
            *(float4*)(ra + 4) = *(const float4*)&As[kk][row0 + 4];
            *(float4*)(rb)     = *(const float4*)&Bs[kk][col0];
            *(float4*)(rb + 4) = *(const float4*)&Bs[kk][col0 + 4];
            #pragma unroll
            for (int i = 0; i < 8; i++)
                #pragma unroll
                for (int j = 0; j < 8; j++)
                    acc[i][j] = fmaf(ra[i], rb[j], acc[i][j]);
        }
        __syncthreads();
    }

    #pragma unroll
    for (int i = 0; i < 8; i++) {
        size_t gm = (size_t)(bm + row0 + i);
        #pragma unroll
        for (int j = 0; j < 8; j++) {
            int gn = bn + col0 + j;
            float val = acc[i][j];
            if (MODE != 3) val += bias[gn];
            if (MODE == 1) val = 0.5f * val * (1.f + erff(val * 0.70710678118654752f));
            if (MODE == 2) val += res[gm * N + gn];
            C[gm * N + gn] = val;
        }
    }
}

// ---------------- causal flash attention (fp32) ------------------------
// grid: (B*H, T/64); block 256. Each block: 64 q-rows of one head.
__global__ void __launch_bounds__(256) attn_kernel(const float* __restrict__ q,
                                                   const float* __restrict__ k,
                                                   const float* __restrict__ v,
                                                   float* __restrict__ y)
{
    __shared__ __align__(16) float Qs[64][68];
    __shared__ __align__(16) float Ks[32][68];
    __shared__ __align__(16) float Vs[32][68];
    __shared__ __align__(16) float Ss[64][36];

    int bh = blockIdx.x;
    int b  = bh / HGPT;
    int h  = bh % HGPT;
    int qb = blockIdx.y;
    int tid = threadIdx.x;

    const float* qbase = q + ((size_t)(b * TGPT + qb * 64)) * DGPT + h * HDH;
    const float* kbase = k + ((size_t)(b * TGPT)) * DGPT + h * HDH;
    const float* vbase = v + ((size_t)(b * TGPT)) * DGPT + h * HDH;

    // load Q tile (64x64)
    for (int f = tid; f < 1024; f += 256) {
        int r = f >> 4, c4 = (f & 15) * 4;
        *(float4*)&Qs[r][c4] = *(const float4*)(qbase + (size_t)r * DGPT + c4);
    }

    int i  = tid >> 2;        // 0..63 q row
    int cg = tid & 3;         // col group
    int d0 = cg * 16;         // output dim base
    int qglob = qb * 64 + i;

    float O[16];
    #pragma unroll
    for (int dd = 0; dd < 16; dd++) O[dd] = 0.f;
    float m_run = -1e30f, l_run = 0.f;

    int nchunks = 2 * qb + 2;       // kv chunks of 32 covering causal span
    __syncthreads();

    for (int ch = 0; ch < nchunks; ch++) {
        int j0 = ch * 32;
        for (int f = tid; f < 512; f += 256) {
            int r = f >> 4, c4 = (f & 15) * 4;
            *(float4*)&Ks[r][c4] = *(const float4*)(kbase + (size_t)(j0 + r) * DGPT + c4);
            *(float4*)&Vs[r][c4] = *(const float4*)(vbase + (size_t)(j0 + r) * DGPT + c4);
        }
        __syncthreads();

        // S = scale * Q K^T (8 cols per thread), causal mask
        float sv[8];
        #pragma unroll
        for (int cc = 0; cc < 8; cc++) sv[cc] = 0.f;
        #pragma unroll 8
        for (int d = 0; d < 64; d++) {
            float qd = Qs[i][d];
            #pragma unroll
            for (int cc = 0; cc < 8; cc++)
                sv[cc] = fmaf(qd, Ks[cg * 8 + cc][d], sv[cc]);
        }
        float mloc = -1e30f;
        #pragma unroll
        for (int cc = 0; cc < 8; cc++) {
            float s = sv[cc] * 0.125f;
            if (j0 + cg * 8 + cc > qglob) s = -1e30f;
            sv[cc] = s;
            mloc = fmaxf(mloc, s);
        }
        mloc = fmaxf(mloc, __shfl_xor_sync(0xffffffffu, mloc, 1));
        mloc = fmaxf(mloc, __shfl_xor_sync(0xffffffffu, mloc, 2));

        float mnew = fmaxf(m_run, mloc);
        float corr = expf(m_run - mnew);
        float psum = 0.f;
        #pragma unroll
        for (int cc = 0; cc < 8; cc++) {
            float p = expf(sv[cc] - mnew);
            Ss[i][cg * 8 + cc] = p;
            psum += p;
        }
        psum += __shfl_xor_sync(0xffffffffu, psum, 1);
        psum += __shfl_xor_sync(0xffffffffu, psum, 2);
        l_run = l_run * corr + psum;
        m_run = mnew;
        #pragma unroll
        for (int dd = 0; dd < 16; dd++) O[dd] *= corr;
        __syncwarp();   // Ss row written by 4 lanes of same warp

        // O += P @ V
        #pragma unroll 4
        for (int c = 0; c < 32; c++) {
            float p = Ss[i][c];
            float4 v0 = *(const float4*)&Vs[c][d0];
            float4 v1 = *(const float4*)&Vs[c][d0 + 4];
            float4 v2 = *(const float4*)&Vs[c][d0 + 8];
            float4 v3 = *(const float4*)&Vs[c][d0 + 12];
            O[0]  = fmaf(p, v0.x, O[0]);  O[1]  = fmaf(p, v0.y, O[1]);
            O[2]  = fmaf(p, v0.z, O[2]);  O[3]  = fmaf(p, v0.w, O[3]);
            O[4]  = fmaf(p, v1.x, O[4]);  O[5]  = fmaf(p, v1.y, O[5]);
            O[6]  = fmaf(p, v1.z, O[6]);  O[7]  = fmaf(p, v1.w, O[7]);
            O[8]  = fmaf(p, v2.x, O[8]);  O[9]  = fmaf(p, v2.y, O[9]);
            O[10] = fmaf(p, v2.z, O[10]); O[11] = fmaf(p, v2.w, O[11]);
            O[12] = fmaf(p, v3.x, O[12]); O[13] = fmaf(p, v3.y, O[13]);
            O[14] = fmaf(p, v3.z, O[14]); O[15] = fmaf(p, v3.w, O[15]);
        }
        __syncthreads();   // before next chunk overwrites Ks/Vs
    }

    float inv = 1.f / l_run;
    float* yp = y + ((size_t)(b * TGPT + qglob)) * DGPT + h * HDH + d0;
    #pragma unroll
    for (int dd = 0; dd < 16; dd++) yp[dd] = O[dd] * inv;
}

// ---------------- launcher ----------------
extern "C" void kernel_launch(void* const* d_in, const int* in_sizes, int n_in,
                              void* d_out, int out_size)
{
    const int*   idx    = (const int*)  d_in[0];
    const float* tok    = (const float*)d_in[1];
    const float* pos    = (const float*)d_in[2];
    const float* ln1_w  = (const float*)d_in[3];
    const float* ln1_b  = (const float*)d_in[4];
    const float* Wq     = (const float*)d_in[5];
    const float* bq     = (const float*)d_in[6];
    const float* Wk     = (const float*)d_in[7];
    const float* bk     = (const float*)d_in[8];
    const float* Wv     = (const float*)d_in[9];
    const float* bv     = (const float*)d_in[10];
    const float* Wproj  = (const float*)d_in[11];
    const float* bproj  = (const float*)d_in[12];
    const float* ln2_w  = (const float*)d_in[13];
    const float* ln2_b  = (const float*)d_in[14];
    const float* W1     = (const float*)d_in[15];
    const float* b1     = (const float*)d_in[16];
    const float* W2     = (const float*)d_in[17];
    const float* b2     = (const float*)d_in[18];
    const float* lnf_w  = (const float*)d_in[19];
    const float* lnf_b  = (const float*)d_in[20];
    const float* Wlogit = (const float*)d_in[21];
    const float* Wdev   = (const float*)d_in[22];
    float* out = (float*)d_out;

    float *xp, *hp, *qp, *kp, *vp, *fp;
    cudaGetSymbolAddress((void**)&xp, g_x);
    cudaGetSymbolAddress((void**)&hp, g_h);
    cudaGetSymbolAddress((void**)&qp, g_q);
    cudaGetSymbolAddress((void**)&kp, g_k);
    cudaGetSymbolAddress((void**)&vp, g_v);
    cudaGetSymbolAddress((void**)&fp, g_ff);

    dim3 gD(DGPT / 128, MGPT / 128);   // N=1024 GEMMs
    dim3 gF(FGPT / 128, MGPT / 128);   // N=4096 GEMMs
    dim3 gV(VGPT / 128, MGPT / 128);   // vocab heads
    dim3 gA(BGPT * HGPT, TGPT / 64);   // attention

    embed_kernel<<<(MGPT * DGPT + 255) / 256, 256>>>(idx, tok, pos, xp);

    for (int l = 0; l < LGPT; l++) {
        size_t oD  = (size_t)l * DGPT * DGPT;
        size_t oF  = (size_t)l * FGPT * DGPT;
        size_t ob  = (size_t)l * DGPT;
        size_t obf = (size_t)l * FGPT;

        ln_kernel<<<MGPT, 256>>>(xp, hp, ln1_w + ob, ln1_b + ob);
        gemm_kernel<0><<<gD, 256>>>(hp, Wq + oD, bq + ob, nullptr, qp, MGPT, DGPT, DGPT);
        gemm_kernel<0><<<gD, 256>>>(hp, Wk + oD, bk + ob, nullptr, kp, MGPT, DGPT, DGPT);
        gemm_kernel<0><<<gD, 256>>>(hp, Wv + oD, bv + ob, nullptr, vp, MGPT, DGPT, DGPT);
        attn_kernel<<<gA, 256>>>(qp, kp, vp, hp);
        gemm_kernel<2><<<gD, 256>>>(hp, Wproj + oD, bproj + ob, xp, xp, MGPT, DGPT, DGPT);

        ln_kernel<<<MGPT, 256>>>(xp, hp, ln2_w + ob, ln2_b + ob);
        gemm_kernel<1><<<gF, 256>>>(hp, W1 + oF, b1 + obf, nullptr, fp, MGPT, FGPT, DGPT);
        gemm_kernel<2><<<gD, 256>>>(fp, W2 + oF, b2 + ob, xp, xp, MGPT, DGPT, FGPT);
    }

    ln_kernel<<<MGPT, 256>>>(xp, hp, lnf_w, lnf_b);
    gemm_kernel<3><<<gV, 256>>>(hp, Wlogit, nullptr, nullptr, out, MGPT, VGPT, DGPT);
    gemm_kernel<3><<<gV, 256>>>(hp, Wdev, nullptr, nullptr, out + (size_t)MGPT * VGPT, MGPT, VGPT, DGPT);
}

// round 2
// speedup vs baseline: 1.6249x; 1.6249x over previous
#include <cuda_runtime.h>
#include <cuda_bf16.h>
#include <math.h>
#include <stdint.h>

// ---------------- problem constants ----------------
#define BGPT 4
#define TGPT 1024
#define DGPT 1024
#define HGPT 16
#define HDH  64
#define LGPT 8
#define VGPT 4096
#define MGPT (BGPT*TGPT)   // 4096 tokens
#define FGPT (4*DGPT)      // 4096 ff dim

// weight scratch offsets (elements)
#define SZ_WQ   ((size_t)LGPT*DGPT*DGPT)      // 8388608
#define SZ_W1   ((size_t)LGPT*FGPT*DGPT)      // 33554432
#define SZ_HEAD ((size_t)VGPT*DGPT)           // 4194304
#define O_WQ    ((size_t)0)
#define O_WK    (O_WQ + SZ_WQ)
#define O_WV    (O_WK + SZ_WQ)
#define O_WP    (O_WV + SZ_WQ)
#define O_W1    (O_WP + SZ_WQ)
#define O_W2    (O_W1 + SZ_W1)
#define O_WLG   (O_W2 + SZ_W1)
#define O_WDV   (O_WLG + SZ_HEAD)
#define WTOT    (O_WDV + SZ_HEAD)             // 109051904 elems

// ---------------- scratch (device globals; no allocs allowed) ----------------
__device__ float g_x [MGPT*DGPT];   // residual stream
__device__ float g_h [MGPT*DGPT];   // LN out / attn out
__device__ float g_q [MGPT*DGPT];
__device__ float g_k [MGPT*DGPT];
__device__ float g_v [MGPT*DGPT];
__device__ float g_ff[MGPT*FGPT];
__device__ __nv_bfloat16 g_whi[WTOT];           // split weights (all tensors)
__device__ __nv_bfloat16 g_wlo[WTOT];
__device__ __nv_bfloat16 g_ahi[(size_t)MGPT*FGPT];  // split activations (max M*4D)
__device__ __nv_bfloat16 g_alo[(size_t)MGPT*FGPT];

// ---------------- embedding ----------------
__global__ void embed_kernel(const int* __restrict__ idx,
                             const float* __restrict__ tok,
                             const float* __restrict__ pos,
                             float* __restrict__ x)
{
    int i = blockIdx.x * blockDim.x + threadIdx.x;
    if (i >= MGPT * DGPT) return;
    int row = i / DGPT;
    int d   = i - row * DGPT;
    int t   = row & (TGPT - 1);
    x[i] = tok[(size_t)idx[row] * DGPT + d] + pos[(size_t)t * DGPT + d];
}

// ---------------- fp32 -> bf16 hi/lo split ----------------
__global__ void __launch_bounds__(256) convsplit_kernel(const float* __restrict__ in,
                                                        __nv_bfloat16* __restrict__ hi,
                                                        __nv_bfloat16* __restrict__ lo,
                                                        size_t n4)   // n/4
{
    size_t i = (size_t)blockIdx.x * blockDim.x + threadIdx.x;
    if (i >= n4) return;
    size_t e = i * 4;
    float4 v = *(const float4*)(in + e);
    __nv_bfloat16 hx = __float2bfloat16_rn(v.x);
    __nv_bfloat16 hy = __float2bfloat16_rn(v.y);
    __nv_bfloat16 hz = __float2bfloat16_rn(v.z);
    __nv_bfloat16 hw = __float2bfloat16_rn(v.w);
    __nv_bfloat16 lx = __float2bfloat16_rn(v.x - __bfloat162float(hx));
    __nv_bfloat16 ly = __float2bfloat16_rn(v.y - __bfloat162float(hy));
    __nv_bfloat16 lz = __float2bfloat16_rn(v.z - __bfloat162float(hz));
    __nv_bfloat16 lw = __float2bfloat16_rn(v.w - __bfloat162float(hw));
    __nv_bfloat162 h01 = __halves2bfloat162(hx, hy);
    __nv_bfloat162 h23 = __halves2bfloat162(hz, hw);
    __nv_bfloat162 l01 = __halves2bfloat162(lx, ly);
    __nv_bfloat162 l23 = __halves2bfloat162(lz, lw);
    uint2 ho, loo;
    ho.x  = *(uint32_t*)&h01; ho.y  = *(uint32_t*)&h23;
    loo.x = *(uint32_t*)&l01; loo.y = *(uint32_t*)&l23;
    *(uint2*)(hi + e) = ho;
    *(uint2*)(lo + e) = loo;
}

// ---------------- layernorm ----------------
__global__ void __launch_bounds__(256) ln_kernel(const float* __restrict__ in,
                                                 float* __restrict__ out,
                                                 const float* __restrict__ w,
                                                 const float* __restrict__ b)
{
    int row = blockIdx.x;
    const float* x = in + (size_t)row * DGPT;
    int tid = threadIdx.x;
    __shared__ float red[8];

    float s = 0.f;
    for (int d = tid; d < DGPT; d += 256) s += x[d];
    #pragma unroll
    for (int o = 16; o; o >>= 1) s += __shfl_xor_sync(0xffffffffu, s, o);
    if ((tid & 31) == 0) red[tid >> 5] = s;
    __syncthreads();
    if (tid < 32) {
        float v = (tid < 8) ? red[tid] : 0.f;
        #pragma unroll
        for (int o = 4; o; o >>= 1) v += __shfl_xor_sync(0xffffffffu, v, o);
        if (tid == 0) red[0] = v;
    }
    __syncthreads();
    float mean = red[0] * (1.f / DGPT);

    float q = 0.f;
    for (int d = tid; d < DGPT; d += 256) { float t = x[d] - mean; q += t * t; }
    __syncthreads();
    #pragma unroll
    for (int o = 16; o; o >>= 1) q += __shfl_xor_sync(0xffffffffu, q, o);
    if ((tid & 31) == 0) red[tid >> 5] = q;
    __syncthreads();
    if (tid < 32) {
        float v = (tid < 8) ? red[tid] : 0.f;
        #pragma unroll
        for (int o = 4; o; o >>= 1) v += __shfl_xor_sync(0xffffffffu, v, o);
        if (tid == 0) red[0] = v;
    }
    __syncthreads();
    float rstd = rsqrtf(red[0] * (1.f / DGPT) + 1e-5f);

    for (int d = tid; d < DGPT; d += 256)
        out[(size_t)row * DGPT + d] = (x[d] - mean) * rstd * w[d] + b[d];
}

// ---------------- tensor-core GEMM helpers ----------------
__device__ __forceinline__ void ldm4(uint32_t r[4], const __nv_bfloat16* p)
{
    uint32_t a = (uint32_t)__cvta_generic_to_shared(p);
    asm volatile("ldmatrix.sync.aligned.m8n8.x4.shared.b16 {%0,%1,%2,%3}, [%4];\n"
                 : "=r"(r[0]), "=r"(r[1]), "=r"(r[2]), "=r"(r[3]) : "r"(a));
}

__device__ __forceinline__ void mma16816(float c[4], const uint32_t a[4], const uint32_t b[2])
{
    asm volatile(
        "mma.sync.aligned.m16n8k16.row.col.f32.bf16.bf16.f32 "
        "{%0,%1,%2,%3}, {%4,%5,%6,%7}, {%8,%9}, {%0,%1,%2,%3};\n"
        : "+f"(c[0]), "+f"(c[1]), "+f"(c[2]), "+f"(c[3])
        : "r"(a[0]), "r"(a[1]), "r"(a[2]), "r"(a[3]), "r"(b[0]), "r"(b[1]));
}

// ---------------- GEMM: C[M,N] = A[M,K] @ W[N,K]^T  (bf16x3, fp32 acc) ----
// MODE: 0 = +bias | 1 = +bias then exact GELU | 2 = +bias +res | 3 = plain
#define BKg 32
#define PK  40
#define SMBUF (128*PK)           // one buffer of one matrix (elems)
#define SMMAT (2*SMBUF)          // double-buffered matrix
#define GSMEM_BYTES (4*SMMAT*2)  // 81920 bytes

template<int MODE>
__global__ void __launch_bounds__(256) gemm_tc(
    const __nv_bfloat16* __restrict__ Ahi, const __nv_bfloat16* __restrict__ Alo,
    const __nv_bfloat16* __restrict__ Whi, const __nv_bfloat16* __restrict__ Wlo,
    const float* __restrict__ bias, const float* __restrict__ res,
    float* __restrict__ C, int M, int N, int K)
{
    extern __shared__ __align__(16) __nv_bfloat16 sm[];
    __nv_bfloat16* sAh = sm;
    __nv_bfloat16* sAl = sm + SMMAT;
    __nv_bfloat16* sBh = sm + 2 * SMMAT;
    __nv_bfloat16* sBl = sm + 3 * SMMAT;

    const int tid  = threadIdx.x;
    const int lane = tid & 31;
    const int wid  = tid >> 5;
    const int wm   = wid >> 2;          // 0..1
    const int wn   = wid & 3;           // 0..3
    const int bm   = blockIdx.y * 128;
    const int bn   = blockIdx.x * 128;

    // global load mapping: 2 threads per row, 16 bf16 (32B) per thread
    const int lrow = tid >> 1;
    const int lcol = (tid & 1) << 4;
    const __nv_bfloat16* gAh = Ahi + (size_t)(bm + lrow) * K + lcol;
    const __nv_bfloat16* gAl = Alo + (size_t)(bm + lrow) * K + lcol;
    const __nv_bfloat16* gBh = Whi + (size_t)(bn + lrow) * K + lcol;
    const __nv_bfloat16* gBl = Wlo + (size_t)(bn + lrow) * K + lcol;

    // ldmatrix geometry
    const int a_r = wm * 64 + (lane & 15);
    const int a_c = (lane >> 4) * 8;
    const int b_r = wn * 32 + (lane >> 4) * 8 + (lane & 7);
    const int b_c = ((lane >> 3) & 1) * 8;

    float acc[4][4][4];
    #pragma unroll
    for (int mi = 0; mi < 4; mi++)
        #pragma unroll
        for (int ni = 0; ni < 4; ni++)
            #pragma unroll
            for (int r = 0; r < 4; r++) acc[mi][ni][r] = 0.f;

    uint4 rAh0, rAh1, rAl0, rAl1, rBh0, rBh1, rBl0, rBl1;

    const int NS = K / BKg;
    // prologue: stage 0
    rAh0 = *(const uint4*)(gAh);     rAh1 = *(const uint4*)(gAh + 8);
    rAl0 = *(const uint4*)(gAl);     rAl1 = *(const uint4*)(gAl + 8);
    rBh0 = *(const uint4*)(gBh);     rBh1 = *(const uint4*)(gBh + 8);
    rBl0 = *(const uint4*)(gBl);     rBl1 = *(const uint4*)(gBl + 8);
    {
        __nv_bfloat16* p = sAh + lrow * PK + lcol;
        *(uint4*)p = rAh0; *(uint4*)(p + 8) = rAh1;
        p = sAl + lrow * PK + lcol;
        *(uint4*)p = rAl0; *(uint4*)(p + 8) = rAl1;
        p = sBh + lrow * PK + lcol;
        *(uint4*)p = rBh0; *(uint4*)(p + 8) = rBh1;
        p = sBl + lrow * PK + lcol;
        *(uint4*)p = rBl0; *(uint4*)(p + 8) = rBl1;
    }
    __syncthreads();

    for (int s = 0; s < NS; s++) {
        if (s + 1 < NS) {
            int k0 = (s + 1) * BKg;
            rAh0 = *(const uint4*)(gAh + k0);  rAh1 = *(const uint4*)(gAh + k0 + 8);
            rAl0 = *(const uint4*)(gAl + k0);  rAl1 = *(const uint4*)(gAl + k0 + 8);
            rBh0 = *(const uint4*)(gBh + k0);  rBh1 = *(const uint4*)(gBh + k0 + 8);
            rBl0 = *(const uint4*)(gBl + k0);  rBl1 = *(const uint4*)(gBl + k0 + 8);
        }

        const int bo = (s & 1) * SMBUF;
        #pragma unroll
        for (int ks = 0; ks < 2; ks++) {
            const int k0 = ks * 16;
            uint32_t afh[4][4], afl[4][4];
            #pragma unroll
            for (int mi = 0; mi < 4; mi++) {
                const int off = bo + (a_r + mi * 16) * PK + k0 + a_c;
                ldm4(afh[mi], sAh + off);
                ldm4(afl[mi], sAl + off);
            }
            uint32_t bfh[4][2], bfl[4][2];
            #pragma unroll
            for (int np = 0; np < 2; np++) {
                const int off = bo + (b_r + np * 16) * PK + k0 + b_c;
                uint32_t t[4];
                ldm4(t, sBh + off);
                bfh[np * 2][0] = t[0]; bfh[np * 2][1] = t[1];
                bfh[np * 2 + 1][0] = t[2]; bfh[np * 2 + 1][1] = t[3];
                ldm4(t, sBl + off);
                bfl[np * 2][0] = t[0]; bfl[np * 2][1] = t[1];
                bfl[np * 2 + 1][0] = t[2]; bfl[np * 2 + 1][1] = t[3];
            }
            #pragma unroll
            for (int mi = 0; mi < 4; mi++)
                #pragma unroll
                for (int ni = 0; ni < 4; ni++) {
                    mma16816(acc[mi][ni], afh[mi], bfh[ni]);
                    mma16816(acc[mi][ni], afh[mi], bfl[ni]);
                    mma16816(acc[mi][ni], afl[mi], bfh[ni]);
                }
        }

        if (s + 1 < NS) {
            const int bo2 = ((s + 1) & 1) * SMBUF;
            __nv_bfloat16* p = sAh + bo2 + lrow * PK + lcol;
            *(uint4*)p = rAh0; *(uint4*)(p + 8) = rAh1;
            p = sAl + bo2 + lrow * PK + lcol;
            *(uint4*)p = rAl0; *(uint4*)(p + 8) = rAl1;
            p = sBh + bo2 + lrow * PK + lcol;
            *(uint4*)p = rBh0; *(uint4*)(p + 8) = rBh1;
            p = sBl + bo2 + lrow * PK + lcol;
            *(uint4*)p = rBl0; *(uint4*)(p + 8) = rBl1;
            __syncthreads();
        }
    }

    // epilogue
    const int er = bm + wm * 64 + (lane >> 2);
    const int ec = bn + wn * 32 + (lane & 3) * 2;
    #pragma unroll
    for (int mi = 0; mi < 4; mi++) {
        #pragma unroll
        for (int ni = 0; ni < 4; ni++) {
            const int col = ec + ni * 8;
            #pragma unroll
            for (int h = 0; h < 2; h++) {       // h=0: row, h=1: row+8
                const size_t row = (size_t)(er + mi * 16 + h * 8);
                float v0 = acc[mi][ni][h * 2];
                float v1 = acc[mi][ni][h * 2 + 1];
                if (MODE != 3) { v0 += bias[col]; v1 += bias[col + 1]; }
                if (MODE == 1) {
                    v0 = 0.5f * v0 * (1.f + erff(v0 * 0.70710678118654752f));
                    v1 = 0.5f * v1 * (1.f + erff(v1 * 0.70710678118654752f));
                }
                if (MODE == 2) {
                    v0 += res[row * N + col];
                    v1 += res[row * N + col + 1];
                }
                float2 o; o.x = v0; o.y = v1;
                *(float2*)(C + row * N + col) = o;
            }
        }
    }
}

// ---------------- causal flash attention (fp32) ------------------------
__global__ void __launch_bounds__(256) attn_kernel(const float* __restrict__ q,
                                                   const float* __restrict__ k,
                                                   const float* __restrict__ v,
                                                   float* __restrict__ y)
{
    __shared__ __align__(16) float Qs[64][68];
    __shared__ __align__(16) float Ks[32][68];
    __shared__ __align__(16) float Vs[32][68];
    __shared__ __align__(16) float Ss[64][36];

    int bh = blockIdx.x;
    int b  = bh / HGPT;
    int h  = bh % HGPT;
    int qb = blockIdx.y;
    int tid = threadIdx.x;

    const float* qbase = q + ((size_t)(b * TGPT + qb * 64)) * DGPT + h * HDH;
    const float* kbase = k + ((size_t)(b * TGPT)) * DGPT + h * HDH;
    const float* vbase = v + ((size_t)(b * TGPT)) * DGPT + h * HDH;

    for (int f = tid; f < 1024; f += 256) {
        int r = f >> 4, c4 = (f & 15) * 4;
        *(float4*)&Qs[r][c4] = *(const float4*)(qbase + (size_t)r * DGPT + c4);
    }

    int i  = tid >> 2;
    int cg = tid & 3;
    int d0 = cg * 16;
    int qglob = qb * 64 + i;

    float O[16];
    #pragma unroll
    for (int dd = 0; dd < 16; dd++) O[dd] = 0.f;
    float m_run = -1e30f, l_run = 0.f;

    int nchunks = 2 * qb + 2;
    __syncthreads();

    for (int ch = 0; ch < nchunks; ch++) {
        int j0 = ch * 32;
        for (int f = tid; f < 512; f += 256) {
            int r = f >> 4, c4 = (f & 15) * 4;
            *(float4*)&Ks[r][c4] = *(const float4*)(kbase + (size_t)(j0 + r) * DGPT + c4);
            *(float4*)&Vs[r][c4] = *(const float4*)(vbase + (size_t)(j0 + r) * DGPT + c4);
        }
        __syncthreads();

        float sv[8];
        #pragma unroll
        for (int cc = 0; cc < 8; cc++) sv[cc] = 0.f;
        #pragma unroll 8
        for (int d = 0; d < 64; d++) {
            float qd = Qs[i][d];
            #pragma unroll
            for (int cc = 0; cc < 8; cc++)
                sv[cc] = fmaf(qd, Ks[cg * 8 + cc][d], sv[cc]);
        }
        float mloc = -1e30f;
        #pragma unroll
        for (int cc = 0; cc < 8; cc++) {
            float s = sv[cc] * 0.125f;
            if (j0 + cg * 8 + cc > qglob) s = -1e30f;
            sv[cc] = s;
            mloc = fmaxf(mloc, s);
        }
        mloc = fmaxf(mloc, __shfl_xor_sync(0xffffffffu, mloc, 1));
        mloc = fmaxf(mloc, __shfl_xor_sync(0xffffffffu, mloc, 2));

        float mnew = fmaxf(m_run, mloc);
        float corr = expf(m_run - mnew);
        float psum = 0.f;
        #pragma unroll
        for (int cc = 0; cc < 8; cc++) {
            float p = expf(sv[cc] - mnew);
            Ss[i][cg * 8 + cc] = p;
            psum += p;
        }
        psum += __shfl_xor_sync(0xffffffffu, psum, 1);
        psum += __shfl_xor_sync(0xffffffffu, psum, 2);
        l_run = l_run * corr + psum;
        m_run = mnew;
        #pragma unroll
        for (int dd = 0; dd < 16; dd++) O[dd] *= corr;
        __syncwarp();

        #pragma unroll 4
        for (int c = 0; c < 32; c++) {
            float p = Ss[i][c];
            float4 v0 = *(const float4*)&Vs[c][d0];
            float4 v1 = *(const float4*)&Vs[c][d0 + 4];
            float4 v2 = *(const float4*)&Vs[c][d0 + 8];
            float4 v3 = *(const float4*)&Vs[c][d0 + 12];
            O[0]  = fmaf(p, v0.x, O[0]);  O[1]  = fmaf(p, v0.y, O[1]);
            O[2]  = fmaf(p, v0.z, O[2]);  O[3]  = fmaf(p, v0.w, O[3]);
            O[4]  = fmaf(p, v1.x, O[4]);  O[5]  = fmaf(p, v1.y, O[5]);
            O[6]  = fmaf(p, v1.z, O[6]);  O[7]  = fmaf(p, v1.w, O[7]);
            O[8]  = fmaf(p, v2.x, O[8]);  O[9]  = fmaf(p, v2.y, O[9]);
            O[10] = fmaf(p, v2.z, O[10]); O[11] = fmaf(p, v2.w, O[11]);
            O[12] = fmaf(p, v3.x, O[12]); O[13] = fmaf(p, v3.y, O[13]);
            O[14] = fmaf(p, v3.z, O[14]); O[15] = fmaf(p, v3.w, O[15]);
        }
        __syncthreads();
    }

    float inv = 1.f / l_run;
    float* yp = y + ((size_t)(b * TGPT + qglob)) * DGPT + h * HDH + d0;
    #pragma unroll
    for (int dd = 0; dd < 16; dd++) yp[dd] = O[dd] * inv;
}

// ---------------- launcher ----------------
static inline void convsplit(const float* in, __nv_bfloat16* hi, __nv_bfloat16* lo, size_t n)
{
    size_t n4 = n / 4;
    convsplit_kernel<<<(unsigned)((n4 + 255) / 256), 256>>>(in, hi, lo, n4);
}

extern "C" void kernel_launch(void* const* d_in, const int* in_sizes, int n_in,
                              void* d_out, int out_size)
{
    const int*   idx    = (const int*)  d_in[0];
    const float* tok    = (const float*)d_in[1];
    const float* pos    = (const float*)d_in[2];
    const float* ln1_w  = (const float*)d_in[3];
    const float* ln1_b  = (const float*)d_in[4];
    const float* Wq     = (const float*)d_in[5];
    const float* bq     = (const float*)d_in[6];
    const float* Wk     = (const float*)d_in[7];
    const float* bk     = (const float*)d_in[8];
    const float* Wv     = (const float*)d_in[9];
    const float* bv     = (const float*)d_in[10];
    const float* Wproj  = (const float*)d_in[11];
    const float* bproj  = (const float*)d_in[12];
    const float* ln2_w  = (const float*)d_in[13];
    const float* ln2_b  = (const float*)d_in[14];
    const float* W1     = (const float*)d_in[15];
    const float* b1     = (const float*)d_in[16];
    const float* W2     = (const float*)d_in[17];
    const float* b2     = (const float*)d_in[18];
    const float* lnf_w  = (const float*)d_in[19];
    const float* lnf_b  = (const float*)d_in[20];
    const float* Wlogit = (const float*)d_in[21];
    const float* Wdev   = (const float*)d_in[22];
    float* out = (float*)d_out;

    float *xp, *hp, *qp, *kp, *vp, *fp;
    __nv_bfloat16 *whi, *wlo, *ahi, *alo;
    cudaGetSymbolAddress((void**)&xp, g_x);
    cudaGetSymbolAddress((void**)&hp, g_h);
    cudaGetSymbolAddress((void**)&qp, g_q);
    cudaGetSymbolAddress((void**)&kp, g_k);
    cudaGetSymbolAddress((void**)&vp, g_v);
    cudaGetSymbolAddress((void**)&fp, g_ff);
    cudaGetSymbolAddress((void**)&whi, g_whi);
    cudaGetSymbolAddress((void**)&wlo, g_wlo);
    cudaGetSymbolAddress((void**)&ahi, g_ahi);
    cudaGetSymbolAddress((void**)&alo, g_alo);

    cudaFuncSetAttribute(gemm_tc<0>, cudaFuncAttributeMaxDynamicSharedMemorySize, GSMEM_BYTES);
    cudaFuncSetAttribute(gemm_tc<1>, cudaFuncAttributeMaxDynamicSharedMemorySize, GSMEM_BYTES);
    cudaFuncSetAttribute(gemm_tc<2>, cudaFuncAttributeMaxDynamicSharedMemorySize, GSMEM_BYTES);
    cudaFuncSetAttribute(gemm_tc<3>, cudaFuncAttributeMaxDynamicSharedMemorySize, GSMEM_BYTES);

    // split all weights once
    convsplit(Wq,     whi + O_WQ,  wlo + O_WQ,  SZ_WQ);
    convsplit(Wk,     whi + O_WK,  wlo + O_WK,  SZ_WQ);
    convsplit(Wv,     whi + O_WV,  wlo + O_WV,  SZ_WQ);
    convsplit(Wproj,  whi + O_WP,  wlo + O_WP,  SZ_WQ);
    convsplit(W1,     whi + O_W1,  wlo + O_W1,  SZ_W1);
    convsplit(W2,     whi + O_W2,  wlo + O_W2,  SZ_W1);
    convsplit(Wlogit, whi + O_WLG, wlo + O_WLG, SZ_HEAD);
    convsplit(Wdev,   whi + O_WDV, wlo + O_WDV, SZ_HEAD);

    dim3 gD(DGPT / 128, MGPT / 128);   // N=1024 GEMMs
    dim3 gF(FGPT / 128, MGPT / 128);   // N=4096 GEMMs
    dim3 gV(VGPT / 128, MGPT / 128);   // vocab heads
    dim3 gA(BGPT * HGPT, TGPT / 64);   // attention

    embed_kernel<<<(MGPT * DGPT + 255) / 256, 256>>>(idx, tok, pos, xp);

    for (int l = 0; l < LGPT; l++) {
        size_t oD  = (size_t)l * DGPT * DGPT;
        size_t oF  = (size_t)l * FGPT * DGPT;
        size_t ob  = (size_t)l * DGPT;
        size_t obf = (size_t)l * FGPT;

        ln_kernel<<<MGPT, 256>>>(xp, hp, ln1_w + ob, ln1_b + ob);
        convsplit(hp, ahi, alo, (size_t)MGPT * DGPT);
        gemm_tc<0><<<gD, 256, GSMEM_BYTES>>>(ahi, alo, whi + O_WQ + oD, wlo + O_WQ + oD,
                                             bq + ob, nullptr, qp, MGPT, DGPT, DGPT);
        gemm_tc<0><<<gD, 256, GSMEM_BYTES>>>(ahi, alo, whi + O_WK + oD, wlo + O_WK + oD,
                                             bk + ob, nullptr, kp, MGPT, DGPT, DGPT);
        gemm_tc<0><<<gD, 256, GSMEM_BYTES>>>(ahi, alo, whi + O_WV + oD, wlo + O_WV + oD,
                                             bv + ob, nullptr, vp, MGPT, DGPT, DGPT);
        attn_kernel<<<gA, 256>>>(qp, kp, vp, hp);
        convsplit(hp, ahi, alo, (size_t)MGPT * DGPT);
        gemm_tc<2><<<gD, 256, GSMEM_BYTES>>>(ahi, alo, whi + O_WP + oD, wlo + O_WP + oD,
                                             bproj + ob, xp, xp, MGPT, DGPT, DGPT);

        ln_kernel<<<MGPT, 256>>>(xp, hp, ln2_w + ob, ln2_b + ob);
        convsplit(hp, ahi, alo, (size_t)MGPT * DGPT);
        gemm_tc<1><<<gF, 256, GSMEM_BYTES>>>(ahi, alo, whi + O_W1 + oF, wlo + O_W1 + oF,
                                             b1 + obf, nullptr, fp, MGPT, FGPT, DGPT);
        convsplit(fp, ahi, alo, (size_t)MGPT * FGPT);
        gemm_tc<2><<<gD, 256, GSMEM_BYTES>>>(ahi, alo, whi + O_W2 + oF, wlo + O_W2 + oF,
                                             b2 + ob, xp, xp, MGPT, DGPT, FGPT);
    }

    ln_kernel<<<MGPT, 256>>>(xp, hp, lnf_w, lnf_b);
    convsplit(hp, ahi, alo, (size_t)MGPT * DGPT);
    gemm_tc<3><<<gV, 256, GSMEM_BYTES>>>(ahi, alo, whi + O_WLG, wlo + O_WLG,
                                         nullptr, nullptr, out, MGPT, VGPT, DGPT);
    gemm_tc<3><<<gV, 256, GSMEM_BYTES>>>(ahi, alo, whi + O_WDV, wlo + O_WDV,
                                         nullptr, nullptr, out + (size_t)MGPT * VGPT, MGPT, VGPT, DGPT);
}

// round 4
// speedup vs baseline: 1.6616x; 1.0226x over previous
#include <cuda_runtime.h>
#include <cuda_bf16.h>
#include <math.h>
#include <stdint.h>

// ---------------- problem constants ----------------
#define BGPT 4
#define TGPT 1024
#define DGPT 1024
#define HGPT 16
#define HDH  64
#define LGPT 8
#define VGPT 4096
#define MGPT (BGPT*TGPT)   // 4096 tokens
#define FGPT (4*DGPT)      // 4096 ff dim

// weight scratch offsets (elements)
#define SZ_WQ   ((size_t)LGPT*DGPT*DGPT)
#define SZ_W1   ((size_t)LGPT*FGPT*DGPT)
#define SZ_HEAD ((size_t)VGPT*DGPT)
#define O_WQ    ((size_t)0)
#define O_WK    (O_WQ + SZ_WQ)
#define O_WV    (O_WK + SZ_WQ)
#define O_WP    (O_WV + SZ_WQ)
#define O_W1    (O_WP + SZ_WQ)
#define O_W2    (O_W1 + SZ_W1)
#define O_WLG   (O_W2 + SZ_W1)
#define O_WDV   (O_WLG + SZ_HEAD)
#define WTOT    (O_WDV + SZ_HEAD)

// ---------------- scratch (device globals; no allocs allowed) ----------------
__device__ float g_x [MGPT*DGPT];                    // residual stream (fp32)
__device__ float g_q [MGPT*DGPT];
__device__ float g_k [MGPT*DGPT];
__device__ float g_v [MGPT*DGPT];
__device__ __nv_bfloat16 g_ahi[(size_t)MGPT*DGPT];   // activation hi (LN out / attn out)
__device__ __nv_bfloat16 g_alo[(size_t)MGPT*DGPT];
__device__ __nv_bfloat16 g_fhi[(size_t)MGPT*FGPT];   // ff activation hi
__device__ __nv_bfloat16 g_flo[(size_t)MGPT*FGPT];
__device__ __nv_bfloat16 g_whi[WTOT];                // split weights
__device__ __nv_bfloat16 g_wlo[WTOT];

// ---------------- helpers ----------------
__device__ __forceinline__ void split_bf16(float v, __nv_bfloat16& h, __nv_bfloat16& l)
{
    h = __float2bfloat16_rn(v);
    l = __float2bfloat16_rn(v - __bfloat162float(h));
}

// ---------------- embedding ----------------
__global__ void embed_kernel(const int* __restrict__ idx,
                             const float* __restrict__ tok,
                             const float* __restrict__ pos,
                             float* __restrict__ x)
{
    int i = blockIdx.x * blockDim.x + threadIdx.x;
    if (i >= MGPT * DGPT) return;
    int row = i / DGPT;
    int d   = i - row * DGPT;
    int t   = row & (TGPT - 1);
    x[i] = tok[(size_t)idx[row] * DGPT + d] + pos[(size_t)t * DGPT + d];
}

// ---------------- fp32 -> bf16 hi/lo split (weights only) ----------------
__global__ void __launch_bounds__(256) convsplit_kernel(const float* __restrict__ in,
                                                        __nv_bfloat16* __restrict__ hi,
                                                        __nv_bfloat16* __restrict__ lo,
                                                        size_t n4)
{
    size_t i = (size_t)blockIdx.x * blockDim.x + threadIdx.x;
    if (i >= n4) return;
    size_t e = i * 4;
    float4 v = *(const float4*)(in + e);
    __nv_bfloat16 hx, hy, hz, hw, lx, ly, lz, lw;
    split_bf16(v.x, hx, lx); split_bf16(v.y, hy, ly);
    split_bf16(v.z, hz, lz); split_bf16(v.w, hw, lw);
    __nv_bfloat162 h01 = __halves2bfloat162(hx, hy);
    __nv_bfloat162 h23 = __halves2bfloat162(hz, hw);
    __nv_bfloat162 l01 = __halves2bfloat162(lx, ly);
    __nv_bfloat162 l23 = __halves2bfloat162(lz, lw);
    uint2 ho, loo;
    ho.x  = *(uint32_t*)&h01; ho.y  = *(uint32_t*)&h23;
    loo.x = *(uint32_t*)&l01; loo.y = *(uint32_t*)&l23;
    *(uint2*)(hi + e) = ho;
    *(uint2*)(lo + e) = loo;
}

// ---------------- layernorm: fp32 in -> bf16 hi/lo out ----------------
__global__ void __launch_bounds__(256) ln_kernel(const float* __restrict__ in,
                                                 __nv_bfloat16* __restrict__ ohi,
                                                 __nv_bfloat16* __restrict__ olo,
                                                 const float* __restrict__ w,
                                                 const float* __restrict__ b)
{
    int row = blockIdx.x;
    const float* x = in + (size_t)row * DGPT;
    int tid = threadIdx.x;
    __shared__ float red[8];

    float s = 0.f;
    for (int d = tid; d < DGPT; d += 256) s += x[d];
    #pragma unroll
    for (int o = 16; o; o >>= 1) s += __shfl_xor_sync(0xffffffffu, s, o);
    if ((tid & 31) == 0) red[tid >> 5] = s;
    __syncthreads();
    if (tid < 32) {
        float v = (tid < 8) ? red[tid] : 0.f;
        #pragma unroll
        for (int o = 4; o; o >>= 1) v += __shfl_xor_sync(0xffffffffu, v, o);
        if (tid == 0) red[0] = v;
    }
    __syncthreads();
    float mean = red[0] * (1.f / DGPT);

    float q = 0.f;
    for (int d = tid; d < DGPT; d += 256) { float t = x[d] - mean; q += t * t; }
    __syncthreads();
    #pragma unroll
    for (int o = 16; o; o >>= 1) q += __shfl_xor_sync(0xffffffffu, q, o);
    if ((tid & 31) == 0) red[tid >> 5] = q;
    __syncthreads();
    if (tid < 32) {
        float v = (tid < 8) ? red[tid] : 0.f;
        #pragma unroll
        for (int o = 4; o; o >>= 1) v += __shfl_xor_sync(0xffffffffu, v, o);
        if (tid == 0) red[0] = v;
    }
    __syncthreads();
    float rstd = rsqrtf(red[0] * (1.f / DGPT) + 1e-5f);

    for (int d = tid; d < DGPT; d += 256) {
        float v = (x[d] - mean) * rstd * w[d] + b[d];
        __nv_bfloat16 h, l;
        split_bf16(v, h, l);
        ohi[(size_t)row * DGPT + d] = h;
        olo[(size_t)row * DGPT + d] = l;
    }
}

// ---------------- tensor-core GEMM helpers ----------------
__device__ __forceinline__ void ldm4(uint32_t r[4], const __nv_bfloat16* p)
{
    uint32_t a = (uint32_t)__cvta_generic_to_shared(p);
    asm volatile("ldmatrix.sync.aligned.m8n8.x4.shared.b16 {%0,%1,%2,%3}, [%4];\n"
                 : "=r"(r[0]), "=r"(r[1]), "=r"(r[2]), "=r"(r[3]) : "r"(a));
}

__device__ __forceinline__ void mma16816(float c[4], const uint32_t a[4], const uint32_t b[2])
{
    asm volatile(
        "mma.sync.aligned.m16n8k16.row.col.f32.bf16.bf16.f32 "
        "{%0,%1,%2,%3}, {%4,%5,%6,%7}, {%8,%9}, {%0,%1,%2,%3};\n"
        : "+f"(c[0]), "+f"(c[1]), "+f"(c[2]), "+f"(c[3])
        : "r"(a[0]), "r"(a[1]), "r"(a[2]), "r"(a[3]), "r"(b[0]), "r"(b[1]));
}

// ---------------- GEMM: C[M,N] = A[M,K] @ W[N,K]^T  (bf16x3, fp32 acc) ----
// MODE: 0 = +bias (fp32 out) | 1 = +bias, GELU, bf16 hi/lo out
//       2 = +bias +res (fp32 out) | 3 = plain fp32 out
#define BKg 32
#define PK  40
#define SMBUF (128*PK)
#define SMMAT (2*SMBUF)
#define GSMEM_BYTES (4*SMMAT*2)  // 81920 bytes

template<int MODE>
__global__ void __launch_bounds__(256) gemm_tc(
    const __nv_bfloat16* __restrict__ Ahi, const __nv_bfloat16* __restrict__ Alo,
    const __nv_bfloat16* __restrict__ Whi, const __nv_bfloat16* __restrict__ Wlo,
    const float* __restrict__ bias, const float* __restrict__ res,
    float* __restrict__ C,
    __nv_bfloat16* __restrict__ Chi, __nv_bfloat16* __restrict__ Clo,
    int M, int N, int K)
{
    extern __shared__ __align__(16) __nv_bfloat16 sm[];
    __nv_bfloat16* sAh = sm;
    __nv_bfloat16* sAl = sm + SMMAT;
    __nv_bfloat16* sBh = sm + 2 * SMMAT;
    __nv_bfloat16* sBl = sm + 3 * SMMAT;

    const int tid  = threadIdx.x;
    const int lane = tid & 31;
    const int wid  = tid >> 5;
    const int wm   = wid >> 2;          // 0..1
    const int wn   = wid & 3;           // 0..3
    const int bm   = blockIdx.y * 128;
    const int bn   = blockIdx.x * 128;

    const int lrow = tid >> 1;
    const int lcol = (tid & 1) << 4;
    const __nv_bfloat16* gAh = Ahi + (size_t)(bm + lrow) * K + lcol;
    const __nv_bfloat16* gAl = Alo + (size_t)(bm + lrow) * K + lcol;
    const __nv_bfloat16* gBh = Whi + (size_t)(bn + lrow) * K + lcol;
    const __nv_bfloat16* gBl = Wlo + (size_t)(bn + lrow) * K + lcol;

    const int a_r = wm * 64 + (lane & 15);
    const int a_c = (lane >> 4) * 8;
    const int b_r = wn * 32 + (lane >> 4) * 8 + (lane & 7);
    const int b_c = ((lane >> 3) & 1) * 8;

    float acc[4][4][4];
    #pragma unroll
    for (int mi = 0; mi < 4; mi++)
        #pragma unroll
        for (int ni = 0; ni < 4; ni++)
            #pragma unroll
            for (int r = 0; r < 4; r++) acc[mi][ni][r] = 0.f;

    uint4 rAh0, rAh1, rAl0, rAl1, rBh0, rBh1, rBl0, rBl1;

    const int NS = K / BKg;
    rAh0 = *(const uint4*)(gAh);     rAh1 = *(const uint4*)(gAh + 8);
    rAl0 = *(const uint4*)(gAl);     rAl1 = *(const uint4*)(gAl + 8);
    rBh0 = *(const uint4*)(gBh);     rBh1 = *(const uint4*)(gBh + 8);
    rBl0 = *(const uint4*)(gBl);     rBl1 = *(const uint4*)(gBl + 8);
    {
        __nv_bfloat16* p = sAh + lrow * PK + lcol;
        *(uint4*)p = rAh0; *(uint4*)(p + 8) = rAh1;
        p = sAl + lrow * PK + lcol;
        *(uint4*)p = rAl0; *(uint4*)(p + 8) = rAl1;
        p = sBh + lrow * PK + lcol;
        *(uint4*)p = rBh0; *(uint4*)(p + 8) = rBh1;
        p = sBl + lrow * PK + lcol;
        *(uint4*)p = rBl0; *(uint4*)(p + 8) = rBl1;
    }
    __syncthreads();

    for (int s = 0; s < NS; s++) {
        if (s + 1 < NS) {
            int k0 = (s + 1) * BKg;
            rAh0 = *(const uint4*)(gAh + k0);  rAh1 = *(const uint4*)(gAh + k0 + 8);
            rAl0 = *(const uint4*)(gAl + k0);  rAl1 = *(const uint4*)(gAl + k0 + 8);
            rBh0 = *(const uint4*)(gBh + k0);  rBh1 = *(const uint4*)(gBh + k0 + 8);
            rBl0 = *(const uint4*)(gBl + k0);  rBl1 = *(const uint4*)(gBl + k0 + 8);
        }

        const int bo = (s & 1) * SMBUF;
        #pragma unroll
        for (int ks = 0; ks < 2; ks++) {
            const int k0 = ks * 16;
            uint32_t afh[4][4], afl[4][4];
            #pragma unroll
            for (int mi = 0; mi < 4; mi++) {
                const int off = bo + (a_r + mi * 16) * PK + k0 + a_c;
                ldm4(afh[mi], sAh + off);
                ldm4(afl[mi], sAl + off);
            }
            uint32_t bfh[4][2], bfl[4][2];
            #pragma unroll
            for (int np = 0; np < 2; np++) {
                const int off = bo + (b_r + np * 16) * PK + k0 + b_c;
                uint32_t t[4];
                ldm4(t, sBh + off);
                bfh[np * 2][0] = t[0]; bfh[np * 2][1] = t[1];
                bfh[np * 2 + 1][0] = t[2]; bfh[np * 2 + 1][1] = t[3];
                ldm4(t, sBl + off);
                bfl[np * 2][0] = t[0]; bfl[np * 2][1] = t[1];
                bfl[np * 2 + 1][0] = t[2]; bfl[np * 2 + 1][1] = t[3];
            }
            // term-outermost ordering: accumulator reuse distance = 16 MMAs
            #pragma unroll
            for (int mi = 0; mi < 4; mi++)
                #pragma unroll
                for (int ni = 0; ni < 4; ni++)
                    mma16816(acc[mi][ni], afh[mi], bfh[ni]);
            #pragma unroll
            for (int mi = 0; mi < 4; mi++)
                #pragma unroll
                for (int ni = 0; ni < 4; ni++)
                    mma16816(acc[mi][ni], afh[mi], bfl[ni]);
            #pragma unroll
            for (int mi = 0; mi < 4; mi++)
                #pragma unroll
                for (int ni = 0; ni < 4; ni++)
                    mma16816(acc[mi][ni], afl[mi], bfh[ni]);
        }

        if (s + 1 < NS) {
            const int bo2 = ((s + 1) & 1) * SMBUF;
            __nv_bfloat16* p = sAh + bo2 + lrow * PK + lcol;
            *(uint4*)p = rAh0; *(uint4*)(p + 8) = rAh1;
            p = sAl + bo2 + lrow * PK + lcol;
            *(uint4*)p = rAl0; *(uint4*)(p + 8) = rAl1;
            p = sBh + bo2 + lrow * PK + lcol;
            *(uint4*)p = rBh0; *(uint4*)(p + 8) = rBh1;
            p = sBl + bo2 + lrow * PK + lcol;
            *(uint4*)p = rBl0; *(uint4*)(p + 8) = rBl1;
            __syncthreads();
        }
    }

    // epilogue
    const int er = bm + wm * 64 + (lane >> 2);
    const int ec = bn + wn * 32 + (lane & 3) * 2;
    #pragma unroll
    for (int mi = 0; mi < 4; mi++) {
        #pragma unroll
        for (int ni = 0; ni < 4; ni++) {
            const int col = ec + ni * 8;
            #pragma unroll
            for (int h = 0; h < 2; h++) {
                const size_t row = (size_t)(er + mi * 16 + h * 8);
                float v0 = acc[mi][ni][h * 2];
                float v1 = acc[mi][ni][h * 2 + 1];
                if (MODE != 3) { v0 += bias[col]; v1 += bias[col + 1]; }
                if (MODE == 1) {
                    v0 = 0.5f * v0 * (1.f + erff(v0 * 0.70710678118654752f));
                    v1 = 0.5f * v1 * (1.f + erff(v1 * 0.70710678118654752f));
                    __nv_bfloat16 h0, l0, h1, l1;
                    split_bf16(v0, h0, l0);
                    split_bf16(v1, h1, l1);
                    *(__nv_bfloat162*)(Chi + row * N + col) = __halves2bfloat162(h0, h1);
                    *(__nv_bfloat162*)(Clo + row * N + col) = __halves2bfloat162(l0, l1);
                } else {
                    if (MODE == 2) {
                        v0 += res[row * N + col];
                        v1 += res[row * N + col + 1];
                    }
                    float2 o; o.x = v0; o.y = v1;
                    *(float2*)(C + row * N + col) = o;
                }
            }
        }
    }
}

// ---------------- causal flash attention (fp32, bf16 hi/lo out) ----------
__global__ void __launch_bounds__(256) attn_kernel(const float* __restrict__ q,
                                                   const float* __restrict__ k,
                                                   const float* __restrict__ v,
                                                   __nv_bfloat16* __restrict__ yhi,
                                                   __nv_bfloat16* __restrict__ ylo)
{
    __shared__ __align__(16) float Qs[64][68];
    __shared__ __align__(16) float Ks[32][68];
    __shared__ __align__(16) float Vs[32][68];
    __shared__ __align__(16) float Ss[64][36];

    int bh = blockIdx.x;
    int b  = bh / HGPT;
    int h  = bh % HGPT;
    int qb = blockIdx.y;
    int tid = threadIdx.x;

    const float* qbase = q + ((size_t)(b * TGPT + qb * 64)) * DGPT + h * HDH;
    const float* kbase = k + ((size_t)(b * TGPT)) * DGPT + h * HDH;
    const float* vbase = v + ((size_t)(b * TGPT)) * DGPT + h * HDH;

    for (int f = tid; f < 1024; f += 256) {
        int r = f >> 4, c4 = (f & 15) * 4;
        *(float4*)&Qs[r][c4] = *(const float4*)(qbase + (size_t)r * DGPT + c4);
    }

    int i  = tid >> 2;
    int cg = tid & 3;
    int d0 = cg * 16;
    int qglob = qb * 64 + i;

    float O[16];
    #pragma unroll
    for (int dd = 0; dd < 16; dd++) O[dd] = 0.f;
    float m_run = -1e30f, l_run = 0.f;

    int nchunks = 2 * qb + 2;
    __syncthreads();

    for (int ch = 0; ch < nchunks; ch++) {
        int j0 = ch * 32;
        for (int f = tid; f < 512; f += 256) {
            int r = f >> 4, c4 = (f & 15) * 4;
            *(float4*)&Ks[r][c4] = *(const float4*)(kbase + (size_t)(j0 + r) * DGPT + c4);
            *(float4*)&Vs[r][c4] = *(const float4*)(vbase + (size_t)(j0 + r) * DGPT + c4);
        }
        __syncthreads();

        float sv[8];
        #pragma unroll
        for (int cc = 0; cc < 8; cc++) sv[cc] = 0.f;
        #pragma unroll 8
        for (int d = 0; d < 64; d++) {
            float qd = Qs[i][d];
            #pragma unroll
            for (int cc = 0; cc < 8; cc++)
                sv[cc] = fmaf(qd, Ks[cg * 8 + cc][d], sv[cc]);
        }
        float mloc = -1e30f;
        #pragma unroll
        for (int cc = 0; cc < 8; cc++) {
            float s = sv[cc] * 0.125f;
            if (j0 + cg * 8 + cc > qglob) s = -1e30f;
            sv[cc] = s;
            mloc = fmaxf(mloc, s);
        }
        mloc = fmaxf(mloc, __shfl_xor_sync(0xffffffffu, mloc, 1));
        mloc = fmaxf(mloc, __shfl_xor_sync(0xffffffffu, mloc, 2));

        float mnew = fmaxf(m_run, mloc);
        float corr = expf(m_run - mnew);
        float psum = 0.f;
        #pragma unroll
        for (int cc = 0; cc < 8; cc++) {
            float p = expf(sv[cc] - mnew);
            Ss[i][cg * 8 + cc] = p;
            psum += p;
        }
        psum += __shfl_xor_sync(0xffffffffu, psum, 1);
        psum += __shfl_xor_sync(0xffffffffu, psum, 2);
        l_run = l_run * corr + psum;
        m_run = mnew;
        #pragma unroll
        for (int dd = 0; dd < 16; dd++) O[dd] *= corr;
        __syncwarp();

        #pragma unroll 4
        for (int c = 0; c < 32; c++) {
            float p = Ss[i][c];
            float4 v0 = *(const float4*)&Vs[c][d0];
            float4 v1 = *(const float4*)&Vs[c][d0 + 4];
            float4 v2 = *(const float4*)&Vs[c][d0 + 8];
            float4 v3 = *(const float4*)&Vs[c][d0 + 12];
            O[0]  = fmaf(p, v0.x, O[0]);  O[1]  = fmaf(p, v0.y, O[1]);
            O[2]  = fmaf(p, v0.z, O[2]);  O[3]  = fmaf(p, v0.w, O[3]);
            O[4]  = fmaf(p, v1.x, O[4]);  O[5]  = fmaf(p, v1.y, O[5]);
            O[6]  = fmaf(p, v1.z, O[6]);  O[7]  = fmaf(p, v1.w, O[7]);
            O[8]  = fmaf(p, v2.x, O[8]);  O[9]  = fmaf(p, v2.y, O[9]);
            O[10] = fmaf(p, v2.z, O[10]); O[11] = fmaf(p, v2.w, O[11]);
            O[12] = fmaf(p, v3.x, O[12]); O[13] = fmaf(p, v3.y, O[13]);
            O[14] = fmaf(p, v3.z, O[14]); O[15] = fmaf(p, v3.w, O[15]);
        }
        __syncthreads();
    }

    float inv = 1.f / l_run;
    size_t base = ((size_t)(b * TGPT + qglob)) * DGPT + h * HDH + d0;
    #pragma unroll
    for (int dd = 0; dd < 16; dd += 2) {
        float v0 = O[dd] * inv;
        float v1 = O[dd + 1] * inv;
        __nv_bfloat16 h0, l0, h1, l1;
        split_bf16(v0, h0, l0);
        split_bf16(v1, h1, l1);
        *(__nv_bfloat162*)(yhi + base + dd) = __halves2bfloat162(h0, h1);
        *(__nv_bfloat162*)(ylo + base + dd) = __halves2bfloat162(l0, l1);
    }
}

// ---------------- launcher ----------------
static inline void convsplit(const float* in, __nv_bfloat16* hi, __nv_bfloat16* lo, size_t n)
{
    size_t n4 = n / 4;
    convsplit_kernel<<<(unsigned)((n4 + 255) / 256), 256>>>(in, hi, lo, n4);
}

extern "C" void kernel_launch(void* const* d_in, const int* in_sizes, int n_in,
                              void* d_out, int out_size)
{
    const int*   idx    = (const int*)  d_in[0];
    const float* tok    = (const float*)d_in[1];
    const float* pos    = (const float*)d_in[2];
    const float* ln1_w  = (const float*)d_in[3];
    const float* ln1_b  = (const float*)d_in[4];
    const float* Wq     = (const float*)d_in[5];
    const float* bq     = (const float*)d_in[6];
    const float* Wk     = (const float*)d_in[7];
    const float* bk     = (const float*)d_in[8];
    const float* Wv     = (const float*)d_in[9];
    const float* bv     = (const float*)d_in[10];
    const float* Wproj  = (const float*)d_in[11];
    const float* bproj  = (const float*)d_in[12];
    const float* ln2_w  = (const float*)d_in[13];
    const float* ln2_b  = (const float*)d_in[14];
    const float* W1     = (const float*)d_in[15];
    const float* b1     = (const float*)d_in[16];
    const float* W2     = (const float*)d_in[17];
    const float* b2     = (const float*)d_in[18];
    const float* lnf_w  = (const float*)d_in[19];
    const float* lnf_b  = (const float*)d_in[20];
    const float* Wlogit = (const float*)d_in[21];
    const float* Wdev   = (const float*)d_in[22];
    float* out = (float*)d_out;

    float *xp, *qp, *kp, *vp;
    __nv_bfloat16 *whi, *wlo, *ahi, *alo, *fhi, *flo;
    cudaGetSymbolAddress((void**)&xp, g_x);
    cudaGetSymbolAddress((void**)&qp, g_q);
    cudaGetSymbolAddress((void**)&kp, g_k);
    cudaGetSymbolAddress((void**)&vp, g_v);
    cudaGetSymbolAddress((void**)&whi, g_whi);
    cudaGetSymbolAddress((void**)&wlo, g_wlo);
    cudaGetSymbolAddress((void**)&ahi, g_ahi);
    cudaGetSymbolAddress((void**)&alo, g_alo);
    cudaGetSymbolAddress((void**)&fhi, g_fhi);
    cudaGetSymbolAddress((void**)&flo, g_flo);

    cudaFuncSetAttribute(gemm_tc<0>, cudaFuncAttributeMaxDynamicSharedMemorySize, GSMEM_BYTES);
    cudaFuncSetAttribute(gemm_tc<1>, cudaFuncAttributeMaxDynamicSharedMemorySize, GSMEM_BYTES);
    cudaFuncSetAttribute(gemm_tc<2>, cudaFuncAttributeMaxDynamicSharedMemorySize, GSMEM_BYTES);
    cudaFuncSetAttribute(gemm_tc<3>, cudaFuncAttributeMaxDynamicSharedMemorySize, GSMEM_BYTES);

    // split all weights once
    convsplit(Wq,     whi + O_WQ,  wlo + O_WQ,  SZ_WQ);
    convsplit(Wk,     whi + O_WK,  wlo + O_WK,  SZ_WQ);
    convsplit(Wv,     whi + O_WV,  wlo + O_WV,  SZ_WQ);
    convsplit(Wproj,  whi + O_WP,  wlo + O_WP,  SZ_WQ);
    convsplit(W1,     whi + O_W1,  wlo + O_W1,  SZ_W1);
    convsplit(W2,     whi + O_W2,  wlo + O_W2,  SZ_W1);
    convsplit(Wlogit, whi + O_WLG, wlo + O_WLG, SZ_HEAD);
    convsplit(Wdev,   whi + O_WDV, wlo + O_WDV, SZ_HEAD);

    dim3 gD(DGPT / 128, MGPT / 128);
    dim3 gF(FGPT / 128, MGPT / 128);
    dim3 gV(VGPT / 128, MGPT / 128);
    dim3 gA(BGPT * HGPT, TGPT / 64);

    embed_kernel<<<(MGPT * DGPT + 255) / 256, 256>>>(idx, tok, pos, xp);

    for (int l = 0; l < LGPT; l++) {
        size_t oD  = (size_t)l * DGPT * DGPT;
        size_t oF  = (size_t)l * FGPT * DGPT;
        size_t ob  = (size_t)l * DGPT;
        size_t obf = (size_t)l * FGPT;

        ln_kernel<<<MGPT, 256>>>(xp, ahi, alo, ln1_w + ob, ln1_b + ob);
        gemm_tc<0><<<gD, 256, GSMEM_BYTES>>>(ahi, alo, whi + O_WQ + oD, wlo + O_WQ + oD,
                                             bq + ob, nullptr, qp, nullptr, nullptr,
                                             MGPT, DGPT, DGPT);
        gemm_tc<0><<<gD, 256, GSMEM_BYTES>>>(ahi, alo, whi + O_WK + oD, wlo + O_WK + oD,
                                             bk + ob, nullptr, kp, nullptr, nullptr,
                                             MGPT, DGPT, DGPT);
        gemm_tc<0><<<gD, 256, GSMEM_BYTES>>>(ahi, alo, whi + O_WV + oD, wlo + O_WV + oD,
                                             bv + ob, nullptr, vp, nullptr, nullptr,
                                             MGPT, DGPT, DGPT);
        attn_kernel<<<gA, 256>>>(qp, kp, vp, ahi, alo);
        gemm_tc<2><<<gD, 256, GSMEM_BYTES>>>(ahi, alo, whi + O_WP + oD, wlo + O_WP + oD,
                                             bproj + ob, xp, xp, nullptr, nullptr,
                                             MGPT, DGPT, DGPT);

        ln_kernel<<<MGPT, 256>>>(xp, ahi, alo, ln2_w + ob, ln2_b + ob);
        gemm_tc<1><<<gF, 256, GSMEM_BYTES>>>(ahi, alo, whi + O_W1 + oF, wlo + O_W1 + oF,
                                             b1 + obf, nullptr, nullptr, fhi, flo,
                                             MGPT, FGPT, DGPT);
        gemm_tc<2><<<gD, 256, GSMEM_BYTES>>>(fhi, flo, whi + O_W2 + oF, wlo + O_W2 + oF,
                                             b2 + ob, xp, xp, nullptr, nullptr,
                                             MGPT, DGPT, FGPT);
    }

    ln_kernel<<<MGPT, 256>>>(xp, ahi, alo, lnf_w, lnf_b);
    gemm_tc<3><<<gV, 256, GSMEM_BYTES>>>(ahi, alo, whi + O_WLG, wlo + O_WLG,
                                         nullptr, nullptr, out, nullptr, nullptr,
                                         MGPT, VGPT, DGPT);
    gemm_tc<3><<<gV, 256, GSMEM_BYTES>>>(ahi, alo, whi + O_WDV, wlo + O_WDV,
                                         nullptr, nullptr, out + (size_t)MGPT * VGPT, nullptr, nullptr,
                                         MGPT, VGPT, DGPT);
}